// round 3
// baseline (speedup 1.0000x reference)
#include <cuda_runtime.h>

// RaySamples volume rendering, round 3: software-pipelined grid-stride.
//
// One warp per ray per iteration (128 samples = 32 float4, one per lane).
// Each warp processes 8 rays over 8 unrolled iterations, prefetching the
// NEXT ray's densities/deltas before computing the current ray, so every
// warp keeps DRAM loads in flight during its entire lifetime (fixes the
// ~60% DRAM duty cycle of the one-shot versions).
//
// Grid = 1024 blocks x 256 threads = 8192 warps, all resident in a single
// wave (launch_bounds(256,7) caps regs at 36 -> >=7 CTAs/SM).
//
// Output: d_out[0:N*K] = weights, d_out[N*K:2N*K] = transmittance.

static constexpr int N_RAYS     = 65536;
static constexpr int F4_PER_RAY = 32;          // K=128 samples / 4
static constexpr int BLOCKS     = 1024;
static constexpr int THREADS    = 256;
static constexpr int WARPS      = BLOCKS * THREADS / 32;  // 8192
static constexpr int ITERS      = N_RAYS / WARPS;         // 8

__global__ void __launch_bounds__(THREADS, 7) ray_samples_kernel(
    const float4* __restrict__ dens,
    const float4* __restrict__ delt,
    float4* __restrict__ w_out,
    float4* __restrict__ t_out)
{
    const int lane = threadIdx.x & 31;
    const int warp = (blockIdx.x * blockDim.x + threadIdx.x) >> 5;

    int idx = warp * F4_PER_RAY + lane;        // this lane's float4 in ray #warp
    const int stride = WARPS * F4_PER_RAY;     // advance one ray per iteration

    // Prologue: load iteration 0
    float4 d0 = __ldcs(&dens[idx]);
    float4 l0 = __ldcs(&delt[idx]);

    #pragma unroll
    for (int it = 0; it < ITERS; ++it) {
        const int nidx = idx + stride;
        float4 d1, l1;
        if (it + 1 < ITERS) {                  // compile-time eliminated on last iter
            d1 = __ldcs(&dens[nidx]);          // prefetch next ray while computing
            l1 = __ldcs(&delt[nidx]);
        }

        // ---- compute current ray ----
        const float dd0 = d0.x * l0.x;
        const float dd1 = d0.y * l0.y;
        const float dd2 = d0.z * l0.z;
        const float dd3 = d0.w * l0.w;

        const float local_sum = (dd0 + dd1) + (dd2 + dd3);

        // Inclusive warp scan of per-lane sums (width 32)
        float scan = local_sum;
        #pragma unroll
        for (int off = 1; off < 32; off <<= 1) {
            float v = __shfl_up_sync(0xffffffffu, scan, off);
            if (lane >= off) scan += v;
        }
        const float excl = scan - local_sum;   // exclusive optical depth at sample 4*lane

        // Per-sample exp(-dd), reused for both alpha and the T chain
        const float e0 = __expf(-dd0);
        const float e1 = __expf(-dd1);
        const float e2 = __expf(-dd2);
        const float e3 = __expf(-dd3);

        const float t0 = __expf(-excl);
        const float t1 = t0 * e0;
        const float t2 = t1 * e1;
        const float t3 = t2 * e2;

        const float4 T = make_float4(t0, t1, t2, t3);
        const float4 W = make_float4((1.0f - e0) * t0,
                                     (1.0f - e1) * t1,
                                     (1.0f - e2) * t2,
                                     (1.0f - e3) * t3);

        __stcs(&w_out[idx], W);
        __stcs(&t_out[idx], T);

        // rotate pipeline
        d0 = d1;
        l0 = l1;
        idx = nidx;
    }
}

extern "C" void kernel_launch(void* const* d_in, const int* in_sizes, int n_in,
                              void* d_out, int out_size)
{
    const float4* dens = (const float4*)d_in[0];  // densities [N, K, 1] fp32
    const float4* delt = (const float4*)d_in[1];  // deltas    [N, K, 1] fp32
    float* out = (float*)d_out;

    const int total_elems = N_RAYS * 128;
    float4* w_out = (float4*)out;                 // weights
    float4* t_out = (float4*)(out + total_elems); // transmittance

    ray_samples_kernel<<<BLOCKS, THREADS>>>(dens, delt, w_out, t_out);
}